// round 8
// baseline (speedup 1.0000x reference)
#include <cuda_runtime.h>
#include <math.h>

#define NC 16
#define MARGIN 0.3f
#define INVALID 0x7fffffff

// ---------------- device-global scratch (zero-init; finalizer resets) ----------
__device__ float    g_sum_rank;
__device__ float    g_sum_per;
__device__ int      g_cnt;
__device__ unsigned g_done;

// Dedup-min: within one load slot the global index rises with lane, so the
// lowest-lane peer holding a given class value owns the warp minimum.
__device__ __forceinline__ void first_update(unsigned w, int i, int* s_first) {
    unsigned peers = __match_any_sync(0xffffffffu, w);
    int leader = __ffs(peers) - 1;
    if (((int)(threadIdx.x & 31) == leader) && w < (unsigned)NC)
        atomicMin(&s_first[w], i);
}

// ---------------- single fused kernel: independent blocks, no cross-block deps --
// Each block: (a) front-batches its ua triple loads + dtype detection + scan
// loads; (b) computes first_idx; (c) redundantly computes the full 16x16
// distance table (warp-per-pair, rows L1-resident); (d) evaluates its triples
// from smem; (e) block-reduces and atomically accumulates. Finalizer block
// writes out and resets scratch for graph replay.
__global__ __launch_bounds__(256) void fused(
    const float* __restrict__ inputs, const void* __restrict__ tm,
    const void* __restrict__ ua, int n_tm, int T, int D,
    float* __restrict__ out)
{
    __shared__ int   s_first[NC];
    __shared__ int   s_tmnz, s_uanz;
    __shared__ float sD[NC * NC];
    __shared__ float sL1[NC * NC];          // log(d + 1) per pair
    __shared__ float srk[8], spr[8];
    __shared__ int   sv[8];

    const int tid = threadIdx.x;
    const int bid = blockIdx.x;

    if (tid < NC) s_first[tid] = INVALID;
    if (tid == 0) { s_tmnz = 0; s_uanz = 0; }
    __syncthreads();

    const unsigned* tw = (const unsigned*)tm;
    const unsigned* uw = (const unsigned*)ua;

    // ---- front batch: all independent loads issued before any consumption.
    // dtype detection: values in [0,16) => int64 arrays have all odd words 0.
    unsigned dt = 0u;
    {
        int w0 = 2 * tid + 1;
        if (w0 < n_tm) dt = tw[w0];
        int w1 = w0 + 512;
        if (w1 < n_tm) dt |= tw[w1];
    }
    unsigned du = uw[2 * tid + 1];          // word < 512 <= 3T: always in-bounds
    // int32-interpretation scan loads (cover i < min(n_tm, 4096))
    unsigned wv[16];
    #pragma unroll
    for (int r = 0; r < 16; r++) {
        int i = r * 256 + tid;
        wv[r] = (i < n_tm) ? tw[i] : ~0u;
    }
    // this thread's 4 triples, vectorized int32 interpretation
    const int t0 = (bid * 256 + tid) * 4;
    int4 q0, q1, q2;
    const bool vec_ok = (t0 + 4 <= T);
    if (vec_ok) {
        const int4* p = (const int4*)(uw + 3 * (size_t)t0);
        q0 = __ldg(p); q1 = __ldg(p + 1); q2 = __ldg(p + 2);
    }

    if (dt) s_tmnz = 1;
    if (du) s_uanz = 1;
    __syncthreads();

    // ---- first-occurrence scan (dedup'd smem atomics)
    if (s_tmnz) {           // int32: speculative loads are the real data
        #pragma unroll
        for (int r = 0; r < 16; r++) first_update(wv[r], r * 256 + tid, s_first);
        for (int i = 4096 + tid; i < n_tm; i += 256)
            first_update(tw[i], i, s_first);
    } else {                // int64: low words at stride 2
        for (int i = tid; i < n_tm; i += 256)
            first_update(tw[2 * i], i, s_first);
    }
    const int ua64 = (s_uanz == 0);
    __syncthreads();

    // ---- 16x16 distance table: warp w handles pairs p = w, w+8, ... (15 each)
    {
        const int wid = tid >> 5, lid = tid & 31;
        const int nv4 = D >> 2;
        for (int p = wid; p < 120; p += 8) {
            int i = 0, rem = p;
            while (rem >= 15 - i) { rem -= 15 - i; i++; }   // row i: 15-i pairs
            int j = i + 1 + rem;
            int fi = s_first[i]; if (fi == INVALID) fi = 0; // argmax all-false==0
            int fj = s_first[j]; if (fj == INVALID) fj = 0;
            const float4* ra = (const float4*)(inputs + (size_t)fi * D);
            const float4* rb = (const float4*)(inputs + (size_t)fj * D);
            float acc = 0.0f;
            for (int k = lid; k < nv4; k += 32) {
                float4 x = __ldg(ra + k);
                float4 y = __ldg(rb + k);
                float d0 = x.x - y.x, d1 = x.y - y.y;
                float d2 = x.z - y.z, d3 = x.w - y.w;
                acc = fmaf(d0, d0, acc); acc = fmaf(d1, d1, acc);
                acc = fmaf(d2, d2, acc); acc = fmaf(d3, d3, acc);
            }
            for (int k = nv4 * 4 + lid; k < D; k += 32) {   // D%4 tail
                float d = __ldg(inputs + (size_t)fi * D + k)
                        - __ldg(inputs + (size_t)fj * D + k);
                acc = fmaf(d, d, acc);
            }
            #pragma unroll
            for (int o = 16; o > 0; o >>= 1) acc += __shfl_xor_sync(~0u, acc, o);
            if (lid == 0) {
                float d  = sqrtf(fmaxf(acc, 1e-12f));
                float l1 = __logf(d + 1.0f);
                sD[i * NC + j]  = d;  sD[j * NC + i]  = d;
                sL1[i * NC + j] = l1; sL1[j * NC + i] = l1;
            }
        }
        if (tid < NC) {                                     // diagonal
            sD[tid * NC + tid]  = 1e-6f;                    // sqrt(clip(0,1e-12))
            sL1[tid * NC + tid] = __logf(1.0f + 1e-6f);
        }
    }
    __syncthreads();

    // ---- triple phase: 4 triples/thread + grid-stride tail.
    //      -log(p_ap + EPS) ~= log(dap+dan+2) - log(dan+1)   (EPS ~1e-8 << p_ap)
    int c[4][3];
    if (!ua64 && vec_ok) {
        c[0][0]=q0.x; c[0][1]=q0.y; c[0][2]=q0.z;
        c[1][0]=q0.w; c[1][1]=q1.x; c[1][2]=q1.y;
        c[2][0]=q1.z; c[2][1]=q1.w; c[2][2]=q2.x;
        c[3][0]=q2.y; c[3][1]=q2.z; c[3][2]=q2.w;
    } else {
        #pragma unroll
        for (int k = 0; k < 4; k++) {
            int t = t0 + k;
            c[k][0] = c[k][1] = c[k][2] = -1;
            if (t < T) {
                if (ua64) {
                    size_t b = (size_t)6 * t;
                    c[k][0] = (int)__ldg(uw + b);
                    c[k][1] = (int)__ldg(uw + b + 2);
                    c[k][2] = (int)__ldg(uw + b + 4);
                } else {
                    size_t b = (size_t)3 * t;
                    c[k][0] = (int)__ldg(uw + b);
                    c[k][1] = (int)__ldg(uw + b + 1);
                    c[k][2] = (int)__ldg(uw + b + 2);
                }
            }
        }
    }

    float rk = 0.0f, pr = 0.0f;
    int v = 0;
    #pragma unroll
    for (int k = 0; k < 4; k++) {
        int a = c[k][0], p = c[k][1], n = c[k][2];
        if ((t0 + k) < T) {
            bool ok = ((unsigned)a < 16u) & ((unsigned)p < 16u) & ((unsigned)n < 16u);
            if (ok && s_first[a] != INVALID && s_first[p] != INVALID
                   && s_first[n] != INVALID) {
                v++;
                float dap = sD[a * NC + p];
                int   ian = a * NC + n;
                float dan = sD[ian];
                rk += fmaxf(dap - dan + MARGIN, 0.0f);
                pr += __logf(dap + dan + 2.0f) - sL1[ian];
            }
        }
    }
    for (int t = gridDim.x * 256 * 4 + bid * 256 + tid; t < T;
         t += gridDim.x * 256) {                           // tail if T > grid*1024
        int a, p, n;
        if (ua64) {
            size_t b = (size_t)6 * t;
            a = (int)__ldg(uw + b); p = (int)__ldg(uw + b + 2); n = (int)__ldg(uw + b + 4);
        } else {
            size_t b = (size_t)3 * t;
            a = (int)__ldg(uw + b); p = (int)__ldg(uw + b + 1); n = (int)__ldg(uw + b + 2);
        }
        bool ok = ((unsigned)a < 16u) & ((unsigned)p < 16u) & ((unsigned)n < 16u);
        if (ok && s_first[a] != INVALID && s_first[p] != INVALID
               && s_first[n] != INVALID) {
            v++;
            float dap = sD[a * NC + p];
            int   ian = a * NC + n;
            float dan = sD[ian];
            rk += fmaxf(dap - dan + MARGIN, 0.0f);
            pr += __logf(dap + dan + 2.0f) - sL1[ian];
        }
    }

    #pragma unroll
    for (int o = 16; o > 0; o >>= 1) {
        rk += __shfl_xor_sync(~0u, rk, o);
        pr += __shfl_xor_sync(~0u, pr, o);
        v  += __shfl_xor_sync(~0u, v,  o);
    }
    int w = tid >> 5;
    if ((tid & 31) == 0) { srk[w] = rk; spr[w] = pr; sv[w] = v; }
    __syncthreads();

    if (tid == 0) {
        float R = 0.0f, P = 0.0f; int V = 0;
        #pragma unroll
        for (int k = 0; k < 8; k++) { R += srk[k]; P += spr[k]; V += sv[k]; }
        atomicAdd(&g_sum_rank, R);
        atomicAdd(&g_sum_per,  P);
        atomicAdd(&g_cnt,      V);
        __threadfence();
        unsigned d = atomicAdd(&g_done, 1u);
        if (d == gridDim.x - 1) {
            float sr  = atomicAdd(&g_sum_rank, 0.0f);
            float sp2 = atomicAdd(&g_sum_per,  0.0f);
            int   cn  = atomicAdd(&g_cnt,      0);
            float nv = fmaxf((float)cn, 1.0f);
            float lh = sr / nv;
            float lp = sp2 / nv;
            out[0] = lh + lp;
            out[1] = lh;
            out[2] = lp;
            g_sum_rank = 0.0f; g_sum_per = 0.0f; g_cnt = 0; g_done = 0u;
        }
    }
}

// ---------------- launch ----------------
// Inputs: 0 preds_mat(f32), 1 preds_sub(f32), 2 inputs(f32 B*D),
// 3 targets_mat(int, B), 4 targets_sub(int, B), 5 user_answers(int, T*3)
extern "C" void kernel_launch(void* const* d_in, const int* in_sizes, int n_in,
                              void* d_out, int out_size) {
    const float* inputs = (const float*)d_in[2];
    const void*  tm     = d_in[3];
    const void*  ua     = d_in[5];
    int n_tm = in_sizes[3];
    int T    = in_sizes[5] / 3;
    int D    = in_sizes[2] / n_tm;

    int nb = (T + 256 * 4 - 1) / (256 * 4);
    if (nb > 148) nb = 148;          // single wave; grid-stride tail covers rest
    if (nb < 1) nb = 1;
    fused<<<nb, 256>>>(inputs, tm, ua, n_tm, T, D, (float*)d_out);
}